// round 2
// baseline (speedup 1.0000x reference)
#include <cuda_runtime.h>
#include <math.h>

// ---------------------------------------------------------------------------
// VQ-VAE forward, fp32 direct convs, GB300 sm_103a
// Buffers (device globals; no cudaMalloc allowed):
//   g_big : 32*128*128*128 f32 (256MB)  — z1 (NCHW) for encoder, reused as h (NHWC) for decoder
//   g_z   : 32*64*64*64   f32 (NHWC)   — encoder latent
//   g_q   : 32*64*64*64   f32 (NHWC)   — quantized latent
// ---------------------------------------------------------------------------

__device__ float g_big[67108864];            // 32*128*128*128
__device__ float g_z[8388608];               // 32*64*64*64 NHWC
__device__ float g_q[8388608];
__device__ float g_part[512];

// ===========================================================================
// conv1: x(32,3,256,256) * enc_w1(128,3,4,4) s2 p1 + b, ReLU -> z1 NCHW(32,128,128,128)
// grid (8,8,32) tiles of 16x16 outputs, block 512 = 256 spatial x 2 oc-groups(64)
// ===========================================================================
__global__ void __launch_bounds__(512) k_conv1(const float* __restrict__ x,
                                               const float* __restrict__ w,
                                               const float* __restrict__ b) {
    __shared__ __align__(16) float w_s[16 * 3 * 128];   // [tap][ic][oc] = 6144
    __shared__ __align__(16) float in_s[3 * 35 * 35 + 1]; // 3675(+pad)
    const int n = blockIdx.z;
    const int Tx = blockIdx.x * 16, Ty = blockIdx.y * 16;
    const int tid = threadIdx.x;

    // weights: w_s[(tap*3+ic)*128+oc] = w[(oc*3+ic)*16+tap]; coalesced float4 over taps
    {
        const float4* w4 = (const float4*)w;
        for (int i = tid; i < 1536; i += 512) {
            int t4 = i & 3, rest = i >> 2;
            int ic = rest % 3, oc = rest / 3;
            float4 v = w4[(oc * 3 + ic) * 4 + t4];
            int base = ((t4 * 4) * 3 + ic) * 128 + oc;
            w_s[base + 0 * 3 * 128] = v.x;
            w_s[base + 1 * 3 * 128] = v.y;
            w_s[base + 2 * 3 * 128] = v.z;
            w_s[base + 3 * 3 * 128] = v.w;
        }
    }
    // input tile 35x35x3, origin (2Ty-1, 2Tx-1)
    const int iy0 = 2 * Ty - 1, ix0 = 2 * Tx - 1;
    for (int i = tid; i < 3675; i += 512) {
        int ic = i / 1225, r = i % 1225;
        int ly = r / 35, lx = r % 35;
        int gy = iy0 + ly, gx = ix0 + lx;
        float v = 0.f;
        if (gy >= 0 && gy < 256 && gx >= 0 && gx < 256)
            v = x[((n * 3 + ic) * 256 + gy) * 256 + gx];
        in_s[i] = v;
    }
    __syncthreads();

    const int s = tid & 255, g = tid >> 8;
    const int sy = s >> 4, sx = s & 15;
    float acc[64];
#pragma unroll
    for (int k = 0; k < 64; k++) acc[k] = 0.f;

    for (int ic = 0; ic < 3; ic++) {
#pragma unroll
        for (int ky = 0; ky < 4; ky++) {
#pragma unroll
            for (int kx = 0; kx < 4; kx++) {
                float iv = in_s[ic * 1225 + (2 * sy + ky) * 35 + (2 * sx + kx)];
                const float4* wp =
                    (const float4*)&w_s[((ky * 4 + kx) * 3 + ic) * 128 + g * 64];
#pragma unroll
                for (int k4 = 0; k4 < 16; k4++) {
                    float4 wv = wp[k4];
                    acc[k4 * 4 + 0] = fmaf(iv, wv.x, acc[k4 * 4 + 0]);
                    acc[k4 * 4 + 1] = fmaf(iv, wv.y, acc[k4 * 4 + 1]);
                    acc[k4 * 4 + 2] = fmaf(iv, wv.z, acc[k4 * 4 + 2]);
                    acc[k4 * 4 + 3] = fmaf(iv, wv.w, acc[k4 * 4 + 3]);
                }
            }
        }
    }
    const int oy = Ty + sy, ox = Tx + sx;
    for (int k = 0; k < 64; k++) {
        int oc = g * 64 + k;
        float v = acc[k] + b[oc];
        g_big[((n * 128 + oc) * 128 + oy) * 128 + ox] = fmaxf(v, 0.f);
    }
}

// ===========================================================================
// conv2: z1 NCHW * enc_w2(64,128,4,4) s2 p1 + b -> g_z NHWC(32,64,64,64)
// grid (4,4,32), block 256, 64 oc accumulators/thread, ic chunked by 8
// dyn shared: in 8*35*35=9800 + w [tap][ic8][oc]=16*8*64=8192  -> 71968 B
// ===========================================================================
__global__ void __launch_bounds__(256) k_conv2(const float* __restrict__ w,
                                               const float* __restrict__ b) {
    extern __shared__ float sm[];
    float* in_s = sm;            // 9800
    float* w_s = sm + 9800;      // 8192 (9800*4 % 16 == 0)
    const int n = blockIdx.z;
    const int Tx = blockIdx.x * 16, Ty = blockIdx.y * 16;
    const int tid = threadIdx.x;
    const int sy = tid >> 4, sx = tid & 15;
    const int iy0 = 2 * Ty - 1, ix0 = 2 * Tx - 1;

    float acc[64];
#pragma unroll
    for (int k = 0; k < 64; k++) acc[k] = 0.f;

    const float4* w4 = (const float4*)w;
    for (int cc = 0; cc < 16; cc++) {
        __syncthreads();
        // weights: w_s[(tap*8+ic8)*64+oc] = w[(oc*128+cc*8+ic8)*16+tap]
        for (int i = tid; i < 2048; i += 256) {
            int t4 = i & 3, ic8 = (i >> 2) & 7, oc = i >> 5;
            float4 v = w4[(oc * 128 + cc * 8 + ic8) * 4 + t4];
            int base = ((t4 * 4) * 8 + ic8) * 64 + oc;
            w_s[base + 0 * 8 * 64] = v.x;
            w_s[base + 1 * 8 * 64] = v.y;
            w_s[base + 2 * 8 * 64] = v.z;
            w_s[base + 3 * 8 * 64] = v.w;
        }
        // input 8 x 35 x 35
        for (int i = tid; i < 9800; i += 256) {
            int ic8 = i / 1225, r = i % 1225;
            int ly = r / 35, lx = r % 35;
            int gy = iy0 + ly, gx = ix0 + lx;
            float v = 0.f;
            if (gy >= 0 && gy < 128 && gx >= 0 && gx < 128)
                v = g_big[((n * 128 + cc * 8 + ic8) * 128 + gy) * 128 + gx];
            in_s[i] = v;
        }
        __syncthreads();

        for (int ic8 = 0; ic8 < 8; ic8++) {
#pragma unroll
            for (int ky = 0; ky < 4; ky++) {
#pragma unroll
                for (int kx = 0; kx < 4; kx++) {
                    float iv = in_s[ic8 * 1225 + (2 * sy + ky) * 35 + (2 * sx + kx)];
                    const float4* wp =
                        (const float4*)&w_s[((ky * 4 + kx) * 8 + ic8) * 64];
#pragma unroll
                    for (int k4 = 0; k4 < 16; k4++) {
                        float4 wv = wp[k4];
                        acc[k4 * 4 + 0] = fmaf(iv, wv.x, acc[k4 * 4 + 0]);
                        acc[k4 * 4 + 1] = fmaf(iv, wv.y, acc[k4 * 4 + 1]);
                        acc[k4 * 4 + 2] = fmaf(iv, wv.z, acc[k4 * 4 + 2]);
                        acc[k4 * 4 + 3] = fmaf(iv, wv.w, acc[k4 * 4 + 3]);
                    }
                }
            }
        }
    }
    const int oy = Ty + sy, ox = Tx + sx;
    float4* zp = (float4*)&g_z[((n * 64 + oy) * 64 + ox) * 64];
#pragma unroll
    for (int k4 = 0; k4 < 16; k4++) {
        float4 v;
        v.x = acc[k4 * 4 + 0] + b[k4 * 4 + 0];
        v.y = acc[k4 * 4 + 1] + b[k4 * 4 + 1];
        v.z = acc[k4 * 4 + 2] + b[k4 * 4 + 2];
        v.w = acc[k4 * 4 + 3] + b[k4 * 4 + 3];
        zp[k4] = v;
    }
}

// ===========================================================================
// VQ: for each of 131072 rows (D=64): argmin_j ||z - c_j||^2, gather, loss partial
// grid 512, block 256. dyn shared: cb 32768 + ccn 512 + red 256 = 134144 B
// ===========================================================================
__global__ void __launch_bounds__(256) k_vq(const float* __restrict__ cb) {
    extern __shared__ float sm[];
    float* cb_s = sm;               // 512*64
    float* ccn = sm + 32768;        // 512
    float* red = ccn + 512;         // 256
    const int tid = threadIdx.x;

    for (int i = tid; i < 32768; i += 256) cb_s[i] = cb[i];
    __syncthreads();
    for (int j = tid; j < 512; j += 256) {
        float s = 0.f;
        const float* cp = &cb_s[j * 64];
        for (int d = 0; d < 64; d++) s = fmaf(cp[d], cp[d], s);
        ccn[j] = s;
    }
    __syncthreads();

    const int i = blockIdx.x * 256 + tid;
    float4 zr[16];
    const float4* zp = (const float4*)&g_z[(size_t)i * 64];
#pragma unroll
    for (int d = 0; d < 16; d++) zr[d] = zp[d];

    float best = 3.4e38f;
    int bi = 0;
    for (int j = 0; j < 512; j++) {
        const float4* cp = (const float4*)&cb_s[j * 64];
        float s = 0.f;
#pragma unroll
        for (int d = 0; d < 16; d++) {
            float4 c = cp[d];
            s = fmaf(zr[d].x, c.x, s);
            s = fmaf(zr[d].y, c.y, s);
            s = fmaf(zr[d].z, c.z, s);
            s = fmaf(zr[d].w, c.w, s);
        }
        float score = ccn[j] - 2.f * s;   // argmin invariant to +||z||^2
        if (score < best) { best = score; bi = j; }
    }

    float4* qp = (float4*)&g_q[(size_t)i * 64];
    const float4* cp = (const float4*)&cb_s[bi * 64];
    float sq = 0.f;
#pragma unroll
    for (int d = 0; d < 16; d++) {
        float4 c = cp[d];
        qp[d] = c;
        float dx = c.x - zr[d].x, dy = c.y - zr[d].y;
        float dz = c.z - zr[d].z, dw = c.w - zr[d].w;
        sq += dx * dx + dy * dy + dz * dz + dw * dw;
    }
    red[tid] = sq;
    __syncthreads();
    for (int st = 128; st > 0; st >>= 1) {
        if (tid < st) red[tid] += red[tid + st];
        __syncthreads();
    }
    if (tid == 0) g_part[blockIdx.x] = red[0];
}

// ===========================================================================
// deconv1: q NHWC(32,64,64,64) ^T-conv dec_w1(64,128,4,4) s2 p1 + b, ReLU
//          -> h NHWC(32,128,128,128) in g_big
// grid (8,8,32), block 512 = 256 spatial x 2 oc-groups(64); ic chunked by 8
// dyn shared: in [pos100][stride68]=6800 + w [tap][ic8][oc]=16384 -> 92736 B
// ===========================================================================
__global__ void __launch_bounds__(512) k_deconv1(const float* __restrict__ w,
                                                 const float* __restrict__ b) {
    extern __shared__ float sm[];
    float* in_s = sm;            // 100*68 = 6800 (padded stride vs bank conflicts)
    float* w_s = sm + 6800;      // 16384 (6800*4 % 16 == 0)
    const int n = blockIdx.z;
    const int Tx = blockIdx.x * 16, Ty = blockIdx.y * 16;
    const int tid = threadIdx.x;
    const int s = tid & 255, g = tid >> 8;
    const int sy = s >> 4, sx = s & 15;
    const int oy = Ty + sy, ox = Tx + sx;

    const int ky0 = (oy + 1) & 1, kx0 = (ox + 1) & 1;
    const int y0 = (Ty >> 1) - 1, x0 = (Tx >> 1) - 1;
    const int lyA = ((oy + 1 - ky0) >> 1) - y0;   // in [1,9]
    const int lxA = ((ox + 1 - kx0) >> 1) - x0;

    // input tile [10][10][64] (zero-padded at edges), ic fastest => coalesced
    for (int i = tid; i < 6400; i += 512) {
        int ic = i & 63, p = i >> 6;
        int ly = p / 10, lx = p % 10;
        int gy = y0 + ly, gx = x0 + lx;
        float v = 0.f;
        if (gy >= 0 && gy < 64 && gx >= 0 && gx < 64)
            v = g_q[(((size_t)n * 64 + gy) * 64 + gx) * 64 + ic];
        in_s[p * 68 + ic] = v;
    }

    float acc[64];
#pragma unroll
    for (int k = 0; k < 64; k++) acc[k] = 0.f;

    const float4* w4 = (const float4*)w;
    for (int cc = 0; cc < 8; cc++) {
        __syncthreads();
        // w_s[(tap*8+ic8)*128+oc] = w[((cc*8+ic8)*128+oc)*16+tap]
        for (int i = tid; i < 4096; i += 512) {
            int t4 = i & 3, oc = (i >> 2) & 127, ic8 = i >> 9;
            float4 v = w4[((cc * 8 + ic8) * 128 + oc) * 4 + t4];
            int base = ((t4 * 4) * 8 + ic8) * 128 + oc;
            w_s[base + 0 * 8 * 128] = v.x;
            w_s[base + 1 * 8 * 128] = v.y;
            w_s[base + 2 * 8 * 128] = v.z;
            w_s[base + 3 * 8 * 128] = v.w;
        }
        __syncthreads();

        for (int ic8 = 0; ic8 < 8; ic8++) {
            int ic = cc * 8 + ic8;
#pragma unroll
            for (int ty = 0; ty < 2; ty++) {
                int ky = ky0 + 2 * ty, ly = lyA - ty;
#pragma unroll
                for (int tx = 0; tx < 2; tx++) {
                    int kx = kx0 + 2 * tx, lx = lxA - tx;
                    float iv = in_s[(ly * 10 + lx) * 68 + ic];
                    const float4* wp =
                        (const float4*)&w_s[((ky * 4 + kx) * 8 + ic8) * 128 + g * 64];
#pragma unroll
                    for (int k4 = 0; k4 < 16; k4++) {
                        float4 wv = wp[k4];
                        acc[k4 * 4 + 0] = fmaf(iv, wv.x, acc[k4 * 4 + 0]);
                        acc[k4 * 4 + 1] = fmaf(iv, wv.y, acc[k4 * 4 + 1]);
                        acc[k4 * 4 + 2] = fmaf(iv, wv.z, acc[k4 * 4 + 2]);
                        acc[k4 * 4 + 3] = fmaf(iv, wv.w, acc[k4 * 4 + 3]);
                    }
                }
            }
        }
    }
    float4* hp = (float4*)&g_big[(((size_t)n * 128 + oy) * 128 + ox) * 128 + g * 64];
#pragma unroll
    for (int k4 = 0; k4 < 16; k4++) {
        float4 v;
        v.x = fmaxf(acc[k4 * 4 + 0] + b[g * 64 + k4 * 4 + 0], 0.f);
        v.y = fmaxf(acc[k4 * 4 + 1] + b[g * 64 + k4 * 4 + 1], 0.f);
        v.z = fmaxf(acc[k4 * 4 + 2] + b[g * 64 + k4 * 4 + 2], 0.f);
        v.w = fmaxf(acc[k4 * 4 + 3] + b[g * 64 + k4 * 4 + 3], 0.f);
        hp[k4] = v;
    }
}

// ===========================================================================
// deconv2: h NHWC(32,128,128,128) ^T-conv dec_w2(128,3,4,4) s2 p1 + b, tanh
//          -> out NCHW(32,3,256,256)
// grid (16,16,32), block 256
// dyn shared: in [pos100][stride132]=13200 + w [tap][oc][ic]=6144 -> 77376 B
// ===========================================================================
__global__ void __launch_bounds__(256) k_deconv2(const float* __restrict__ w,
                                                 const float* __restrict__ b,
                                                 float* __restrict__ out) {
    extern __shared__ float sm[];
    float* in_s = sm;             // 100*132 = 13200
    float* w_s = sm + 13200;      // 6144 (13200*4 % 16 == 0)
    const int n = blockIdx.z;
    const int Tx = blockIdx.x * 16, Ty = blockIdx.y * 16;
    const int tid = threadIdx.x;
    const int sy = tid >> 4, sx = tid & 15;
    const int oy = Ty + sy, ox = Tx + sx;
    const int y0 = (Ty >> 1) - 1, x0 = (Tx >> 1) - 1;

    // weights: w_s[(tap*3+oc)*128+ic] = w[(ic*3+oc)*16+tap]
    {
        const float4* w4 = (const float4*)w;
        for (int i = tid; i < 1536; i += 256) {
            int t4 = i & 3, rest = i >> 2;
            int oc = rest % 3, ic = rest / 3;
            float4 v = w4[(ic * 3 + oc) * 4 + t4];
            int base = ((t4 * 4) * 3 + oc) * 128 + ic;
            w_s[base + 0 * 3 * 128] = v.x;
            w_s[base + 1 * 3 * 128] = v.y;
            w_s[base + 2 * 3 * 128] = v.z;
            w_s[base + 3 * 3 * 128] = v.w;
        }
    }
    // input tile [10][10][128], padded stride 132
    for (int i = tid; i < 12800; i += 256) {
        int ic = i & 127, p = i >> 7;
        int ly = p / 10, lx = p % 10;
        int gy = y0 + ly, gx = x0 + lx;
        float v = 0.f;
        if (gy >= 0 && gy < 128 && gx >= 0 && gx < 128)
            v = g_big[(((size_t)n * 128 + gy) * 128 + gx) * 128 + ic];
        in_s[p * 132 + ic] = v;
    }
    __syncthreads();

    const int ky0 = (oy + 1) & 1, kx0 = (ox + 1) & 1;
    const int lyA = ((oy + 1 - ky0) >> 1) - y0;
    const int lxA = ((ox + 1 - kx0) >> 1) - x0;

    float a0 = 0.f, a1 = 0.f, a2 = 0.f;
#pragma unroll
    for (int ty = 0; ty < 2; ty++) {
        int ky = ky0 + 2 * ty, ly = lyA - ty;
#pragma unroll
        for (int tx = 0; tx < 2; tx++) {
            int kx = kx0 + 2 * tx, lx = lxA - tx;
            const float4* ip = (const float4*)&in_s[(ly * 10 + lx) * 132];
            const float4* w0 = (const float4*)&w_s[((ky * 4 + kx) * 3 + 0) * 128];
            const float4* w1 = (const float4*)&w_s[((ky * 4 + kx) * 3 + 1) * 128];
            const float4* w2 = (const float4*)&w_s[((ky * 4 + kx) * 3 + 2) * 128];
#pragma unroll 8
            for (int c4 = 0; c4 < 32; c4++) {
                float4 iv = ip[c4];
                float4 v0 = w0[c4], v1 = w1[c4], v2 = w2[c4];
                a0 += iv.x * v0.x + iv.y * v0.y + iv.z * v0.z + iv.w * v0.w;
                a1 += iv.x * v1.x + iv.y * v1.y + iv.z * v1.z + iv.w * v1.w;
                a2 += iv.x * v2.x + iv.y * v2.y + iv.z * v2.z + iv.w * v2.w;
            }
        }
    }
    out[(((size_t)n * 3 + 0) * 256 + oy) * 256 + ox] = tanhf(a0 + b[0]);
    out[(((size_t)n * 3 + 1) * 256 + oy) * 256 + ox] = tanhf(a1 + b[1]);
    out[(((size_t)n * 3 + 2) * 256 + oy) * 256 + ox] = tanhf(a2 + b[2]);
}

// deterministic loss finalize: vq_loss = 1.25 * sum / (131072*64)
__global__ void k_loss(float* __restrict__ out, int out_size) {
    __shared__ float red[256];
    int tid = threadIdx.x;
    red[tid] = g_part[tid] + g_part[tid + 256];
    __syncthreads();
    for (int st = 128; st > 0; st >>= 1) {
        if (tid < st) red[tid] += red[tid + st];
        __syncthreads();
    }
    if (tid == 0) out[out_size - 1] = 1.25f * red[0] / 8388608.0f;
}

extern "C" void kernel_launch(void* const* d_in, const int* in_sizes, int n_in,
                              void* d_out, int out_size) {
    const float* x   = (const float*)d_in[0];
    const float* ew1 = (const float*)d_in[1];
    const float* eb1 = (const float*)d_in[2];
    const float* ew2 = (const float*)d_in[3];
    const float* eb2 = (const float*)d_in[4];
    const float* cb  = (const float*)d_in[5];
    const float* dw1 = (const float*)d_in[6];
    const float* db1 = (const float*)d_in[7];
    const float* dw2 = (const float*)d_in[8];
    const float* db2 = (const float*)d_in[9];
    float* out = (float*)d_out;

    const int smem_conv2   = (9800 + 8192) * 4;
    const int smem_vq      = (32768 + 512 + 256) * 4;
    const int smem_deconv1 = (6800 + 16384) * 4;
    const int smem_deconv2 = (13200 + 6144) * 4;

    cudaFuncSetAttribute(k_conv2, cudaFuncAttributeMaxDynamicSharedMemorySize, smem_conv2);
    cudaFuncSetAttribute(k_vq, cudaFuncAttributeMaxDynamicSharedMemorySize, smem_vq);
    cudaFuncSetAttribute(k_deconv1, cudaFuncAttributeMaxDynamicSharedMemorySize, smem_deconv1);
    cudaFuncSetAttribute(k_deconv2, cudaFuncAttributeMaxDynamicSharedMemorySize, smem_deconv2);

    k_conv1<<<dim3(8, 8, 32), 512>>>(x, ew1, eb1);
    k_conv2<<<dim3(4, 4, 32), 256, smem_conv2>>>(ew2, eb2);
    k_vq<<<512, 256, smem_vq>>>(cb);
    k_deconv1<<<dim3(8, 8, 32), 512, smem_deconv1>>>(dw1, db1);
    k_deconv2<<<dim3(16, 16, 32), 256, smem_deconv2>>>(dw2, db2, out);
    k_loss<<<1, 256>>>(out, out_size);
}

// round 3
// speedup vs baseline: 1.0256x; 1.0256x over previous
#include <cuda_runtime.h>
#include <math.h>

// ---------------------------------------------------------------------------
// VQ-VAE forward, fp32 (packed f32x2 FMA) direct convs, GB300 sm_103a
// ---------------------------------------------------------------------------

typedef unsigned long long u64;

__device__ __forceinline__ u64 bcast2(float v) {
    u64 r; asm("mov.b64 %0, {%1, %1};" : "=l"(r) : "f"(v)); return r;
}
__device__ __forceinline__ void fma2(u64& d, u64 a, u64 b) {
    asm("fma.rn.f32x2 %0, %1, %2, %0;" : "+l"(d) : "l"(a), "l"(b));
}
__device__ __forceinline__ float2 unpack2(u64 v) {
    float2 r; asm("mov.b64 {%0, %1}, %2;" : "=f"(r.x), "=f"(r.y) : "l"(v)); return r;
}

__device__ float g_big[67108864];            // 32*128*128*128
__device__ float g_z[8388608];               // 32*64*64*64 NHWC
__device__ float g_q[8388608];
__device__ float g_part[512];

// ===========================================================================
// conv1: x(32,3,256,256) * enc_w1(128,3,4,4) s2 p1 + b, ReLU -> z1 NCHW
// grid (8,8,32), block 512 = 256 spatial x 2 oc-groups(64)
// ===========================================================================
__global__ void __launch_bounds__(512) k_conv1(const float* __restrict__ x,
                                               const float* __restrict__ w,
                                               const float* __restrict__ b) {
    __shared__ __align__(16) float w_s[16 * 3 * 128];      // [tap][ic][oc]
    __shared__ __align__(16) float in_s[3 * 35 * 35 + 1];
    const int n = blockIdx.z;
    const int Tx = blockIdx.x * 16, Ty = blockIdx.y * 16;
    const int tid = threadIdx.x;

    {
        const float4* w4 = (const float4*)w;
        for (int i = tid; i < 1536; i += 512) {
            int t4 = i & 3, rest = i >> 2;
            int ic = rest % 3, oc = rest / 3;
            float4 v = w4[(oc * 3 + ic) * 4 + t4];
            int base = ((t4 * 4) * 3 + ic) * 128 + oc;
            w_s[base + 0 * 3 * 128] = v.x;
            w_s[base + 1 * 3 * 128] = v.y;
            w_s[base + 2 * 3 * 128] = v.z;
            w_s[base + 3 * 3 * 128] = v.w;
        }
    }
    const int iy0 = 2 * Ty - 1, ix0 = 2 * Tx - 1;
    for (int i = tid; i < 3675; i += 512) {
        int ic = i / 1225, r = i % 1225;
        int ly = r / 35, lx = r % 35;
        int gy = iy0 + ly, gx = ix0 + lx;
        float v = 0.f;
        if (gy >= 0 && gy < 256 && gx >= 0 && gx < 256)
            v = x[((n * 3 + ic) * 256 + gy) * 256 + gx];
        in_s[i] = v;
    }
    __syncthreads();

    const int s = tid & 255, g = tid >> 8;
    const int sy = s >> 4, sx = s & 15;
    u64 acc[32];
#pragma unroll
    for (int k = 0; k < 32; k++) acc[k] = 0ull;

    for (int ic = 0; ic < 3; ic++) {
#pragma unroll
        for (int ky = 0; ky < 4; ky++) {
#pragma unroll
            for (int kx = 0; kx < 4; kx++) {
                u64 iv2 = bcast2(in_s[ic * 1225 + (2 * sy + ky) * 35 + (2 * sx + kx)]);
                const ulonglong2* wp =
                    (const ulonglong2*)&w_s[((ky * 4 + kx) * 3 + ic) * 128 + g * 64];
#pragma unroll
                for (int k = 0; k < 16; k++) {
                    ulonglong2 wv = wp[k];
                    fma2(acc[2 * k + 0], iv2, wv.x);
                    fma2(acc[2 * k + 1], iv2, wv.y);
                }
            }
        }
    }
    const int oy = Ty + sy, ox = Tx + sx;
#pragma unroll
    for (int k = 0; k < 32; k++) {
        float2 v = unpack2(acc[k]);
        int oc = g * 64 + 2 * k;
        g_big[((n * 128 + oc) * 128 + oy) * 128 + ox]       = fmaxf(v.x + b[oc], 0.f);
        g_big[((n * 128 + oc + 1) * 128 + oy) * 128 + ox]   = fmaxf(v.y + b[oc + 1], 0.f);
    }
}

// ===========================================================================
// conv2: z1 NCHW * enc_w2(64,128,4,4) s2 p1 + b -> g_z NHWC(32,64,64,64)
// grid (4,4,32), block 256; ic chunked by 8
// ===========================================================================
__global__ void __launch_bounds__(256) k_conv2(const float* __restrict__ w,
                                               const float* __restrict__ b) {
    extern __shared__ float sm[];
    float* in_s = sm;            // 9800
    float* w_s = sm + 9800;      // 8192
    const int n = blockIdx.z;
    const int Tx = blockIdx.x * 16, Ty = blockIdx.y * 16;
    const int tid = threadIdx.x;
    const int sy = tid >> 4, sx = tid & 15;
    const int iy0 = 2 * Ty - 1, ix0 = 2 * Tx - 1;

    u64 acc[32];
#pragma unroll
    for (int k = 0; k < 32; k++) acc[k] = 0ull;

    const float4* w4 = (const float4*)w;
    for (int cc = 0; cc < 16; cc++) {
        __syncthreads();
        for (int i = tid; i < 2048; i += 256) {
            int t4 = i & 3, ic8 = (i >> 2) & 7, oc = i >> 5;
            float4 v = w4[(oc * 128 + cc * 8 + ic8) * 4 + t4];
            int base = ((t4 * 4) * 8 + ic8) * 64 + oc;
            w_s[base + 0 * 8 * 64] = v.x;
            w_s[base + 1 * 8 * 64] = v.y;
            w_s[base + 2 * 8 * 64] = v.z;
            w_s[base + 3 * 8 * 64] = v.w;
        }
        for (int i = tid; i < 9800; i += 256) {
            int ic8 = i / 1225, r = i % 1225;
            int ly = r / 35, lx = r % 35;
            int gy = iy0 + ly, gx = ix0 + lx;
            float v = 0.f;
            if (gy >= 0 && gy < 128 && gx >= 0 && gx < 128)
                v = g_big[((n * 128 + cc * 8 + ic8) * 128 + gy) * 128 + gx];
            in_s[i] = v;
        }
        __syncthreads();

        for (int ic8 = 0; ic8 < 8; ic8++) {
#pragma unroll
            for (int ky = 0; ky < 4; ky++) {
#pragma unroll
                for (int kx = 0; kx < 4; kx++) {
                    u64 iv2 = bcast2(in_s[ic8 * 1225 + (2 * sy + ky) * 35 + (2 * sx + kx)]);
                    const ulonglong2* wp =
                        (const ulonglong2*)&w_s[((ky * 4 + kx) * 8 + ic8) * 64];
#pragma unroll
                    for (int k = 0; k < 16; k++) {
                        ulonglong2 wv = wp[k];
                        fma2(acc[2 * k + 0], iv2, wv.x);
                        fma2(acc[2 * k + 1], iv2, wv.y);
                    }
                }
            }
        }
    }
    const int oy = Ty + sy, ox = Tx + sx;
    float4* zp = (float4*)&g_z[((n * 64 + oy) * 64 + ox) * 64];
#pragma unroll
    for (int k = 0; k < 16; k++) {
        float2 p0 = unpack2(acc[2 * k]), p1 = unpack2(acc[2 * k + 1]);
        float4 v;
        v.x = p0.x + b[4 * k + 0];
        v.y = p0.y + b[4 * k + 1];
        v.z = p1.x + b[4 * k + 2];
        v.w = p1.y + b[4 * k + 3];
        zp[k] = v;
    }
}

// ===========================================================================
// VQ: argmin over 512 codes (D=64), gather, loss partial
// grid 512, block 256. dyn smem: cb 32768 + ccn 512 + red 256
// ===========================================================================
__global__ void __launch_bounds__(256) k_vq(const float* __restrict__ cb) {
    extern __shared__ float sm[];
    float* cb_s = sm;               // 512*64
    float* ccn = sm + 32768;        // 512
    float* red = ccn + 512;         // 256
    const int tid = threadIdx.x;

    for (int i = tid; i < 32768; i += 256) cb_s[i] = cb[i];
    __syncthreads();
    for (int j = tid; j < 512; j += 256) {
        float s = 0.f;
        const float* cp = &cb_s[j * 64];
        for (int d = 0; d < 64; d++) s = fmaf(cp[d], cp[d], s);
        ccn[j] = s;
    }
    __syncthreads();

    const int i = blockIdx.x * 256 + tid;
    u64 zr[32];
    {
        const ulonglong2* zp = (const ulonglong2*)&g_z[(size_t)i * 64];
#pragma unroll
        for (int d = 0; d < 16; d++) {
            ulonglong2 t = zp[d];
            zr[2 * d] = t.x; zr[2 * d + 1] = t.y;
        }
    }

    float best = 3.4e38f;
    int bi = 0;
    for (int j = 0; j < 512; j++) {
        const ulonglong2* cp = (const ulonglong2*)&cb_s[j * 64];
        u64 s2 = 0ull;
#pragma unroll
        for (int d = 0; d < 16; d++) {
            ulonglong2 c = cp[d];
            fma2(s2, zr[2 * d], c.x);
            fma2(s2, zr[2 * d + 1], c.y);
        }
        float2 ss = unpack2(s2);
        float score = ccn[j] - 2.f * (ss.x + ss.y);
        if (score < best) { best = score; bi = j; }
    }

    float4* qp = (float4*)&g_q[(size_t)i * 64];
    const float4* cp4 = (const float4*)&cb_s[bi * 64];
    const float4* zp4 = (const float4*)&g_z[(size_t)i * 64];
    float sq = 0.f;
#pragma unroll
    for (int d = 0; d < 16; d++) {
        float4 c = cp4[d], z = zp4[d];
        qp[d] = c;
        float dx = c.x - z.x, dy = c.y - z.y;
        float dz = c.z - z.z, dw = c.w - z.w;
        sq += dx * dx + dy * dy + dz * dz + dw * dw;
    }
    red[tid] = sq;
    __syncthreads();
    for (int st = 128; st > 0; st >>= 1) {
        if (tid < st) red[tid] += red[tid + st];
        __syncthreads();
    }
    if (tid == 0) g_part[blockIdx.x] = red[0];
}

// ===========================================================================
// deconv1: q NHWC ^T-conv dec_w1(64,128,4,4) s2 p1 + b, ReLU -> h NHWC in g_big
// grid (8,8,32), block 512; ic chunked by 8
// ===========================================================================
__global__ void __launch_bounds__(512) k_deconv1(const float* __restrict__ w,
                                                 const float* __restrict__ b) {
    extern __shared__ float sm[];
    float* in_s = sm;            // 100*68 = 6800
    float* w_s = sm + 6800;      // 16384
    const int n = blockIdx.z;
    const int Tx = blockIdx.x * 16, Ty = blockIdx.y * 16;
    const int tid = threadIdx.x;
    const int s = tid & 255, g = tid >> 8;
    const int sy = s >> 4, sx = s & 15;
    const int oy = Ty + sy, ox = Tx + sx;

    const int ky0 = (oy + 1) & 1, kx0 = (ox + 1) & 1;
    const int y0 = (Ty >> 1) - 1, x0 = (Tx >> 1) - 1;
    const int lyA = ((oy + 1 - ky0) >> 1) - y0;
    const int lxA = ((ox + 1 - kx0) >> 1) - x0;

    for (int i = tid; i < 6400; i += 512) {
        int ic = i & 63, p = i >> 6;
        int ly = p / 10, lx = p % 10;
        int gy = y0 + ly, gx = x0 + lx;
        float v = 0.f;
        if (gy >= 0 && gy < 64 && gx >= 0 && gx < 64)
            v = g_q[(((size_t)n * 64 + gy) * 64 + gx) * 64 + ic];
        in_s[p * 68 + ic] = v;
    }

    u64 acc[32];
#pragma unroll
    for (int k = 0; k < 32; k++) acc[k] = 0ull;

    const float4* w4 = (const float4*)w;
    for (int cc = 0; cc < 8; cc++) {
        __syncthreads();
        for (int i = tid; i < 4096; i += 512) {
            int t4 = i & 3, oc = (i >> 2) & 127, ic8 = i >> 9;
            float4 v = w4[((cc * 8 + ic8) * 128 + oc) * 4 + t4];
            int base = ((t4 * 4) * 8 + ic8) * 128 + oc;
            w_s[base + 0 * 8 * 128] = v.x;
            w_s[base + 1 * 8 * 128] = v.y;
            w_s[base + 2 * 8 * 128] = v.z;
            w_s[base + 3 * 8 * 128] = v.w;
        }
        __syncthreads();

        for (int ic8 = 0; ic8 < 8; ic8++) {
            int ic = cc * 8 + ic8;
#pragma unroll
            for (int ty = 0; ty < 2; ty++) {
                int ky = ky0 + 2 * ty, ly = lyA - ty;
#pragma unroll
                for (int tx = 0; tx < 2; tx++) {
                    int kx = kx0 + 2 * tx, lx = lxA - tx;
                    u64 iv2 = bcast2(in_s[(ly * 10 + lx) * 68 + ic]);
                    const ulonglong2* wp =
                        (const ulonglong2*)&w_s[((ky * 4 + kx) * 8 + ic8) * 128 + g * 64];
#pragma unroll
                    for (int k = 0; k < 16; k++) {
                        ulonglong2 wv = wp[k];
                        fma2(acc[2 * k + 0], iv2, wv.x);
                        fma2(acc[2 * k + 1], iv2, wv.y);
                    }
                }
            }
        }
    }
    float4* hp = (float4*)&g_big[(((size_t)n * 128 + oy) * 128 + ox) * 128 + g * 64];
#pragma unroll
    for (int k = 0; k < 16; k++) {
        float2 p0 = unpack2(acc[2 * k]), p1 = unpack2(acc[2 * k + 1]);
        float4 v;
        v.x = fmaxf(p0.x + b[g * 64 + 4 * k + 0], 0.f);
        v.y = fmaxf(p0.y + b[g * 64 + 4 * k + 1], 0.f);
        v.z = fmaxf(p1.x + b[g * 64 + 4 * k + 2], 0.f);
        v.w = fmaxf(p1.y + b[g * 64 + 4 * k + 3], 0.f);
        hp[k] = v;
    }
}

// ===========================================================================
// deconv2: h NHWC ^T-conv dec_w2(128,3,4,4) s2 p1 + b, tanh -> out NCHW
// grid (16,16,32), block 256
// ===========================================================================
__global__ void __launch_bounds__(256) k_deconv2(const float* __restrict__ w,
                                                 const float* __restrict__ b,
                                                 float* __restrict__ out) {
    extern __shared__ float sm[];
    float* in_s = sm;             // 100*132 = 13200
    float* w_s = sm + 13200;      // 6144
    const int n = blockIdx.z;
    const int Tx = blockIdx.x * 16, Ty = blockIdx.y * 16;
    const int tid = threadIdx.x;
    const int sy = tid >> 4, sx = tid & 15;
    const int oy = Ty + sy, ox = Tx + sx;
    const int y0 = (Ty >> 1) - 1, x0 = (Tx >> 1) - 1;

    {
        const float4* w4 = (const float4*)w;
        for (int i = tid; i < 1536; i += 256) {
            int t4 = i & 3, rest = i >> 2;
            int oc = rest % 3, ic = rest / 3;
            float4 v = w4[(ic * 3 + oc) * 4 + t4];
            int base = ((t4 * 4) * 3 + oc) * 128 + ic;
            w_s[base + 0 * 3 * 128] = v.x;
            w_s[base + 1 * 3 * 128] = v.y;
            w_s[base + 2 * 3 * 128] = v.z;
            w_s[base + 3 * 3 * 128] = v.w;
        }
    }
    for (int i = tid; i < 12800; i += 256) {
        int ic = i & 127, p = i >> 7;
        int ly = p / 10, lx = p % 10;
        int gy = y0 + ly, gx = x0 + lx;
        float v = 0.f;
        if (gy >= 0 && gy < 128 && gx >= 0 && gx < 128)
            v = g_big[(((size_t)n * 128 + gy) * 128 + gx) * 128 + ic];
        in_s[p * 132 + ic] = v;
    }
    __syncthreads();

    const int ky0 = (oy + 1) & 1, kx0 = (ox + 1) & 1;
    const int lyA = ((oy + 1 - ky0) >> 1) - y0;
    const int lxA = ((ox + 1 - kx0) >> 1) - x0;

    u64 a0 = 0ull, a1 = 0ull, a2 = 0ull;
#pragma unroll
    for (int ty = 0; ty < 2; ty++) {
        int ky = ky0 + 2 * ty, ly = lyA - ty;
#pragma unroll
        for (int tx = 0; tx < 2; tx++) {
            int kx = kx0 + 2 * tx, lx = lxA - tx;
            const ulonglong2* ip = (const ulonglong2*)&in_s[(ly * 10 + lx) * 132];
            const ulonglong2* w0 = (const ulonglong2*)&w_s[((ky * 4 + kx) * 3 + 0) * 128];
            const ulonglong2* w1 = (const ulonglong2*)&w_s[((ky * 4 + kx) * 3 + 1) * 128];
            const ulonglong2* w2 = (const ulonglong2*)&w_s[((ky * 4 + kx) * 3 + 2) * 128];
#pragma unroll 8
            for (int c = 0; c < 32; c++) {
                ulonglong2 iv = ip[c];
                ulonglong2 v0 = w0[c], v1 = w1[c], v2 = w2[c];
                fma2(a0, iv.x, v0.x); fma2(a0, iv.y, v0.y);
                fma2(a1, iv.x, v1.x); fma2(a1, iv.y, v1.y);
                fma2(a2, iv.x, v2.x); fma2(a2, iv.y, v2.y);
            }
        }
    }
    float2 r0 = unpack2(a0), r1 = unpack2(a1), r2 = unpack2(a2);
    out[(((size_t)n * 3 + 0) * 256 + oy) * 256 + ox] = tanhf(r0.x + r0.y + b[0]);
    out[(((size_t)n * 3 + 1) * 256 + oy) * 256 + ox] = tanhf(r1.x + r1.y + b[1]);
    out[(((size_t)n * 3 + 2) * 256 + oy) * 256 + ox] = tanhf(r2.x + r2.y + b[2]);
}

// deterministic loss finalize: vq_loss = 1.25 * sum / (131072*64)
__global__ void k_loss(float* __restrict__ out, int out_size) {
    __shared__ float red[256];
    int tid = threadIdx.x;
    red[tid] = g_part[tid] + g_part[tid + 256];
    __syncthreads();
    for (int st = 128; st > 0; st >>= 1) {
        if (tid < st) red[tid] += red[tid + st];
        __syncthreads();
    }
    if (tid == 0) out[out_size - 1] = 1.25f * red[0] / 8388608.0f;
}

extern "C" void kernel_launch(void* const* d_in, const int* in_sizes, int n_in,
                              void* d_out, int out_size) {
    const float* x   = (const float*)d_in[0];
    const float* ew1 = (const float*)d_in[1];
    const float* eb1 = (const float*)d_in[2];
    const float* ew2 = (const float*)d_in[3];
    const float* eb2 = (const float*)d_in[4];
    const float* cb  = (const float*)d_in[5];
    const float* dw1 = (const float*)d_in[6];
    const float* db1 = (const float*)d_in[7];
    const float* dw2 = (const float*)d_in[8];
    const float* db2 = (const float*)d_in[9];
    float* out = (float*)d_out;

    const int smem_conv2   = (9800 + 8192) * 4;
    const int smem_vq      = (32768 + 512 + 256) * 4;
    const int smem_deconv1 = (6800 + 16384) * 4;
    const int smem_deconv2 = (13200 + 6144) * 4;

    cudaFuncSetAttribute(k_conv2, cudaFuncAttributeMaxDynamicSharedMemorySize, smem_conv2);
    cudaFuncSetAttribute(k_vq, cudaFuncAttributeMaxDynamicSharedMemorySize, smem_vq);
    cudaFuncSetAttribute(k_deconv1, cudaFuncAttributeMaxDynamicSharedMemorySize, smem_deconv1);
    cudaFuncSetAttribute(k_deconv2, cudaFuncAttributeMaxDynamicSharedMemorySize, smem_deconv2);

    k_conv1<<<dim3(8, 8, 32), 512>>>(x, ew1, eb1);
    k_conv2<<<dim3(4, 4, 32), 256, smem_conv2>>>(ew2, eb2);
    k_vq<<<512, 256, smem_vq>>>(cb);
    k_deconv1<<<dim3(8, 8, 32), 512, smem_deconv1>>>(dw1, db1);
    k_deconv2<<<dim3(16, 16, 32), 256, smem_deconv2>>>(dw2, db2, out);
    k_loss<<<1, 256>>>(out, out_size);
}

// round 4
// speedup vs baseline: 1.2503x; 1.2191x over previous
#include <cuda_runtime.h>
#include <math.h>

// ---------------------------------------------------------------------------
// VQ-VAE forward, fp32 (packed f32x2 FMA), 4-position register blocking
// GB300 sm_103a
// ---------------------------------------------------------------------------

typedef unsigned long long u64;

__device__ __forceinline__ u64 bcast2(float v) {
    u64 r; asm("mov.b64 %0, {%1, %1};" : "=l"(r) : "f"(v)); return r;
}
__device__ __forceinline__ void fma2(u64& d, u64 a, u64 b) {
    asm("fma.rn.f32x2 %0, %1, %2, %0;" : "+l"(d) : "l"(a), "l"(b));
}
__device__ __forceinline__ float2 unpack2(u64 v) {
    float2 r; asm("mov.b64 {%0, %1}, %2;" : "=f"(r.x), "=f"(r.y) : "l"(v)); return r;
}

__device__ float g_big[67108864];            // 32*128*128*128
__device__ float g_z[8388608];               // 32*64*64*64 NHWC
__device__ float g_q[8388608];
__device__ float g_part[512];

// ===========================================================================
// conv1: x(32,3,256,256) * enc_w1(128,3,4,4) s2 p1 + b, ReLU -> z1 NCHW
// grid (8,8,32), block 512: g=tid>>6 (8 oc-groups of 16), 4 positions/thread
// ===========================================================================
__global__ void __launch_bounds__(512) k_conv1(const float* __restrict__ x,
                                               const float* __restrict__ w,
                                               const float* __restrict__ b) {
    __shared__ __align__(16) float w_s[16 * 3 * 128];      // [tap][ic][oc]
    __shared__ __align__(16) float in_s[3 * 35 * 35 + 1];
    const int n = blockIdx.z;
    const int Tx = blockIdx.x * 16, Ty = blockIdx.y * 16;
    const int tid = threadIdx.x;

    {
        const float4* w4 = (const float4*)w;
        for (int i = tid; i < 1536; i += 512) {
            int t4 = i & 3, rest = i >> 2;
            int ic = rest % 3, oc = rest / 3;
            float4 v = w4[(oc * 3 + ic) * 4 + t4];
            int base = ((t4 * 4) * 3 + ic) * 128 + oc;
            w_s[base + 0 * 3 * 128] = v.x;
            w_s[base + 1 * 3 * 128] = v.y;
            w_s[base + 2 * 3 * 128] = v.z;
            w_s[base + 3 * 3 * 128] = v.w;
        }
    }
    const int iy0 = 2 * Ty - 1, ix0 = 2 * Tx - 1;
    for (int i = tid; i < 3675; i += 512) {
        int ic = i / 1225, r = i % 1225;
        int ly = r / 35, lx = r % 35;
        int gy = iy0 + ly, gx = ix0 + lx;
        float v = 0.f;
        if (gy >= 0 && gy < 256 && gx >= 0 && gx < 256)
            v = x[((n * 3 + ic) * 256 + gy) * 256 + gx];
        in_s[i] = v;
    }
    __syncthreads();

    const int g = tid >> 6, p = tid & 63;
    const int py = p >> 3, px = p & 7;
    const int oc16 = g * 16;

    u64 acc[4][8];
#pragma unroll
    for (int pp = 0; pp < 4; pp++)
#pragma unroll
        for (int k = 0; k < 8; k++) acc[pp][k] = 0ull;

    for (int ic = 0; ic < 3; ic++) {
#pragma unroll
        for (int ky = 0; ky < 4; ky++) {
#pragma unroll
            for (int kx = 0; kx < 4; kx++) {
                const ulonglong2* wp =
                    (const ulonglong2*)&w_s[((ky * 4 + kx) * 3 + ic) * 128 + oc16];
                ulonglong2 w0 = wp[0], w1 = wp[1], w2 = wp[2], w3 = wp[3];
#pragma unroll
                for (int pp = 0; pp < 4; pp++) {
                    int yy = py + (pp >> 1) * 8, xx = px + (pp & 1) * 8;
                    u64 iv = bcast2(in_s[ic * 1225 + (2 * yy + ky) * 35 + 2 * xx + kx]);
                    fma2(acc[pp][0], iv, w0.x); fma2(acc[pp][1], iv, w0.y);
                    fma2(acc[pp][2], iv, w1.x); fma2(acc[pp][3], iv, w1.y);
                    fma2(acc[pp][4], iv, w2.x); fma2(acc[pp][5], iv, w2.y);
                    fma2(acc[pp][6], iv, w3.x); fma2(acc[pp][7], iv, w3.y);
                }
            }
        }
    }
#pragma unroll
    for (int pp = 0; pp < 4; pp++) {
        int oy = Ty + py + (pp >> 1) * 8, ox = Tx + px + (pp & 1) * 8;
#pragma unroll
        for (int k = 0; k < 8; k++) {
            float2 v = unpack2(acc[pp][k]);
            int oc = oc16 + 2 * k;
            g_big[((n * 128 + oc) * 128 + oy) * 128 + ox]     = fmaxf(v.x + b[oc], 0.f);
            g_big[((n * 128 + oc + 1) * 128 + oy) * 128 + ox] = fmaxf(v.y + b[oc + 1], 0.f);
        }
    }
}

// ===========================================================================
// conv2: z1 NCHW * enc_w2(64,128,4,4) s2 p1 + b -> g_z NHWC(32,64,64,64)
// grid (4,4,32), block 256: g=tid>>6 (4 oc-groups of 16), 4 positions/thread
// ===========================================================================
__global__ void __launch_bounds__(256) k_conv2(const float* __restrict__ w,
                                               const float* __restrict__ b) {
    extern __shared__ float sm[];
    float* in_s = sm;            // 9800
    float* w_s = sm + 9800;      // 8192
    const int n = blockIdx.z;
    const int Tx = blockIdx.x * 16, Ty = blockIdx.y * 16;
    const int tid = threadIdx.x;
    const int g = tid >> 6, p = tid & 63;
    const int py = p >> 3, px = p & 7;
    const int oc16 = g * 16;
    const int iy0 = 2 * Ty - 1, ix0 = 2 * Tx - 1;

    u64 acc[4][8];
#pragma unroll
    for (int pp = 0; pp < 4; pp++)
#pragma unroll
        for (int k = 0; k < 8; k++) acc[pp][k] = 0ull;

    const float4* w4 = (const float4*)w;
    for (int cc = 0; cc < 16; cc++) {
        __syncthreads();
        for (int i = tid; i < 2048; i += 256) {
            int t4 = i & 3, ic8 = (i >> 2) & 7, oc = i >> 5;
            float4 v = w4[(oc * 128 + cc * 8 + ic8) * 4 + t4];
            int base = ((t4 * 4) * 8 + ic8) * 64 + oc;
            w_s[base + 0 * 8 * 64] = v.x;
            w_s[base + 1 * 8 * 64] = v.y;
            w_s[base + 2 * 8 * 64] = v.z;
            w_s[base + 3 * 8 * 64] = v.w;
        }
        for (int i = tid; i < 9800; i += 256) {
            int ic8 = i / 1225, r = i % 1225;
            int ly = r / 35, lx = r % 35;
            int gy = iy0 + ly, gx = ix0 + lx;
            float v = 0.f;
            if (gy >= 0 && gy < 128 && gx >= 0 && gx < 128)
                v = g_big[((n * 128 + cc * 8 + ic8) * 128 + gy) * 128 + gx];
            in_s[i] = v;
        }
        __syncthreads();

        for (int ic8 = 0; ic8 < 8; ic8++) {
#pragma unroll
            for (int ky = 0; ky < 4; ky++) {
#pragma unroll
                for (int kx = 0; kx < 4; kx++) {
                    const ulonglong2* wp =
                        (const ulonglong2*)&w_s[((ky * 4 + kx) * 8 + ic8) * 64 + oc16];
                    ulonglong2 w0 = wp[0], w1 = wp[1], w2 = wp[2], w3 = wp[3];
#pragma unroll
                    for (int pp = 0; pp < 4; pp++) {
                        int yy = py + (pp >> 1) * 8, xx = px + (pp & 1) * 8;
                        u64 iv = bcast2(in_s[ic8 * 1225 + (2 * yy + ky) * 35 + 2 * xx + kx]);
                        fma2(acc[pp][0], iv, w0.x); fma2(acc[pp][1], iv, w0.y);
                        fma2(acc[pp][2], iv, w1.x); fma2(acc[pp][3], iv, w1.y);
                        fma2(acc[pp][4], iv, w2.x); fma2(acc[pp][5], iv, w2.y);
                        fma2(acc[pp][6], iv, w3.x); fma2(acc[pp][7], iv, w3.y);
                    }
                }
            }
        }
    }
#pragma unroll
    for (int pp = 0; pp < 4; pp++) {
        int oy = Ty + py + (pp >> 1) * 8, ox = Tx + px + (pp & 1) * 8;
        float4* zp = (float4*)&g_z[((n * 64 + oy) * 64 + ox) * 64 + oc16];
#pragma unroll
        for (int k = 0; k < 4; k++) {
            float2 p0 = unpack2(acc[pp][2 * k]), p1 = unpack2(acc[pp][2 * k + 1]);
            float4 v;
            v.x = p0.x + b[oc16 + 4 * k + 0];
            v.y = p0.y + b[oc16 + 4 * k + 1];
            v.z = p1.x + b[oc16 + 4 * k + 2];
            v.w = p1.y + b[oc16 + 4 * k + 3];
            zp[k] = v;
        }
    }
}

// ===========================================================================
// VQ: argmin over 512 codes (D=64), gather, loss partial
// ===========================================================================
__global__ void __launch_bounds__(256) k_vq(const float* __restrict__ cb) {
    extern __shared__ float sm[];
    float* cb_s = sm;               // 512*64
    float* ccn = sm + 32768;        // 512
    float* red = ccn + 512;         // 256
    const int tid = threadIdx.x;

    for (int i = tid; i < 32768; i += 256) cb_s[i] = cb[i];
    __syncthreads();
    for (int j = tid; j < 512; j += 256) {
        float s = 0.f;
        const float* cp = &cb_s[j * 64];
        for (int d = 0; d < 64; d++) s = fmaf(cp[d], cp[d], s);
        ccn[j] = s;
    }
    __syncthreads();

    const int i = blockIdx.x * 256 + tid;
    u64 zr[32];
    {
        const ulonglong2* zp = (const ulonglong2*)&g_z[(size_t)i * 64];
#pragma unroll
        for (int d = 0; d < 16; d++) {
            ulonglong2 t = zp[d];
            zr[2 * d] = t.x; zr[2 * d + 1] = t.y;
        }
    }

    float best = 3.4e38f;
    int bi = 0;
    for (int j = 0; j < 512; j++) {
        const ulonglong2* cp = (const ulonglong2*)&cb_s[j * 64];
        u64 s2 = 0ull;
#pragma unroll
        for (int d = 0; d < 16; d++) {
            ulonglong2 c = cp[d];
            fma2(s2, zr[2 * d], c.x);
            fma2(s2, zr[2 * d + 1], c.y);
        }
        float2 ss = unpack2(s2);
        float score = ccn[j] - 2.f * (ss.x + ss.y);
        if (score < best) { best = score; bi = j; }
    }

    float4* qp = (float4*)&g_q[(size_t)i * 64];
    const float4* cp4 = (const float4*)&cb_s[bi * 64];
    const float4* zp4 = (const float4*)&g_z[(size_t)i * 64];
    float sq = 0.f;
#pragma unroll
    for (int d = 0; d < 16; d++) {
        float4 c = cp4[d], z = zp4[d];
        qp[d] = c;
        float dx = c.x - z.x, dy = c.y - z.y;
        float dz = c.z - z.z, dw = c.w - z.w;
        sq += dx * dx + dy * dy + dz * dz + dw * dw;
    }
    red[tid] = sq;
    __syncthreads();
    for (int st = 128; st > 0; st >>= 1) {
        if (tid < st) red[tid] += red[tid + st];
        __syncthreads();
    }
    if (tid == 0) g_part[blockIdx.x] = red[0];
}

// ===========================================================================
// deconv1: q NHWC ^T-conv dec_w1(64,128,4,4) s2 p1 + b, ReLU -> h NHWC
// grid (8,8,32), block 512: g=tid>>6 (8 oc-groups of 16), 4 positions/thread
// ===========================================================================
__global__ void __launch_bounds__(512) k_deconv1(const float* __restrict__ w,
                                                 const float* __restrict__ b) {
    extern __shared__ float sm[];
    float* in_s = sm;            // 100*68 = 6800
    float* w_s = sm + 6800;      // 16384
    const int n = blockIdx.z;
    const int Tx = blockIdx.x * 16, Ty = blockIdx.y * 16;
    const int tid = threadIdx.x;
    const int g = tid >> 6, p = tid & 63;
    const int py = p >> 3, px = p & 7;
    const int oc16 = g * 16;

    const int oyb = Ty + py, oxb = Tx + px;
    const int ky0 = (oyb + 1) & 1, kx0 = (oxb + 1) & 1;
    const int y0 = (Ty >> 1) - 1, x0 = (Tx >> 1) - 1;
    const int lyA0 = ((oyb + 1 - ky0) >> 1) - y0;   // +4 per 8-row step
    const int lxA0 = ((oxb + 1 - kx0) >> 1) - x0;

    for (int i = tid; i < 6400; i += 512) {
        int ic = i & 63, pos = i >> 6;
        int ly = pos / 10, lx = pos % 10;
        int gy = y0 + ly, gx = x0 + lx;
        float v = 0.f;
        if (gy >= 0 && gy < 64 && gx >= 0 && gx < 64)
            v = g_q[(((size_t)n * 64 + gy) * 64 + gx) * 64 + ic];
        in_s[pos * 68 + ic] = v;
    }

    u64 acc[4][8];
#pragma unroll
    for (int pp = 0; pp < 4; pp++)
#pragma unroll
        for (int k = 0; k < 8; k++) acc[pp][k] = 0ull;

    const float4* w4 = (const float4*)w;
    for (int cc = 0; cc < 8; cc++) {
        __syncthreads();
        for (int i = tid; i < 4096; i += 512) {
            int t4 = i & 3, oc = (i >> 2) & 127, ic8 = i >> 9;
            float4 v = w4[((cc * 8 + ic8) * 128 + oc) * 4 + t4];
            int base = ((t4 * 4) * 8 + ic8) * 128 + oc;
            w_s[base + 0 * 8 * 128] = v.x;
            w_s[base + 1 * 8 * 128] = v.y;
            w_s[base + 2 * 8 * 128] = v.z;
            w_s[base + 3 * 8 * 128] = v.w;
        }
        __syncthreads();

        for (int ic8 = 0; ic8 < 8; ic8++) {
            int ic = cc * 8 + ic8;
#pragma unroll
            for (int ty = 0; ty < 2; ty++) {
                int ky = ky0 + 2 * ty;
#pragma unroll
                for (int tx = 0; tx < 2; tx++) {
                    int kx = kx0 + 2 * tx;
                    const ulonglong2* wp =
                        (const ulonglong2*)&w_s[((ky * 4 + kx) * 8 + ic8) * 128 + oc16];
                    ulonglong2 w0 = wp[0], w1 = wp[1], w2 = wp[2], w3 = wp[3];
#pragma unroll
                    for (int pp = 0; pp < 4; pp++) {
                        int ly = lyA0 + (pp >> 1) * 4 - ty;
                        int lx = lxA0 + (pp & 1) * 4 - tx;
                        u64 iv = bcast2(in_s[(ly * 10 + lx) * 68 + ic]);
                        fma2(acc[pp][0], iv, w0.x); fma2(acc[pp][1], iv, w0.y);
                        fma2(acc[pp][2], iv, w1.x); fma2(acc[pp][3], iv, w1.y);
                        fma2(acc[pp][4], iv, w2.x); fma2(acc[pp][5], iv, w2.y);
                        fma2(acc[pp][6], iv, w3.x); fma2(acc[pp][7], iv, w3.y);
                    }
                }
            }
        }
    }
#pragma unroll
    for (int pp = 0; pp < 4; pp++) {
        int oy = oyb + (pp >> 1) * 8, ox = oxb + (pp & 1) * 8;
        float4* hp = (float4*)&g_big[(((size_t)n * 128 + oy) * 128 + ox) * 128 + oc16];
#pragma unroll
        for (int k = 0; k < 4; k++) {
            float2 p0 = unpack2(acc[pp][2 * k]), p1 = unpack2(acc[pp][2 * k + 1]);
            float4 v;
            v.x = fmaxf(p0.x + b[oc16 + 4 * k + 0], 0.f);
            v.y = fmaxf(p0.y + b[oc16 + 4 * k + 1], 0.f);
            v.z = fmaxf(p1.x + b[oc16 + 4 * k + 2], 0.f);
            v.w = fmaxf(p1.y + b[oc16 + 4 * k + 3], 0.f);
            hp[k] = v;
        }
    }
}

// ===========================================================================
// deconv2: h NHWC ^T-conv dec_w2(128,3,4,4) s2 p1 + b, tanh -> out NCHW
// grid (8,16,32), tile 16 rows x 32 cols, block 256: 2 positions/thread
// dyn smem: in [180 pos][132] = 23760 + w 6144 -> 119616 B
// ===========================================================================
__global__ void __launch_bounds__(256) k_deconv2(const float* __restrict__ w,
                                                 const float* __restrict__ b,
                                                 float* __restrict__ out) {
    extern __shared__ float sm[];
    float* in_s = sm;             // 180*132 = 23760
    float* w_s = sm + 23760;      // 6144
    const int n = blockIdx.z;
    const int Tx = blockIdx.x * 32, Ty = blockIdx.y * 16;
    const int tid = threadIdx.x;
    const int py = tid >> 4, px = tid & 15;
    const int oy = Ty + py, ox = Tx + px;
    const int y0 = (Ty >> 1) - 1, x0 = (Tx >> 1) - 1;

    {
        const float4* w4 = (const float4*)w;
        for (int i = tid; i < 1536; i += 256) {
            int t4 = i & 3, rest = i >> 2;
            int oc = rest % 3, ic = rest / 3;
            float4 v = w4[(ic * 3 + oc) * 4 + t4];
            int base = ((t4 * 4) * 3 + oc) * 128 + ic;
            w_s[base + 0 * 3 * 128] = v.x;
            w_s[base + 1 * 3 * 128] = v.y;
            w_s[base + 2 * 3 * 128] = v.z;
            w_s[base + 3 * 3 * 128] = v.w;
        }
    }
    // input tile [10 rows][18 cols][128 ch], padded stride 132
    for (int i = tid; i < 23040; i += 256) {
        int ic = i & 127, pos = i >> 7;
        int ly = pos / 18, lx = pos % 18;
        int gy = y0 + ly, gx = x0 + lx;
        float v = 0.f;
        if (gy >= 0 && gy < 128 && gx >= 0 && gx < 128)
            v = g_big[(((size_t)n * 128 + gy) * 128 + gx) * 128 + ic];
        in_s[pos * 132 + ic] = v;
    }
    __syncthreads();

    const int ky0 = (oy + 1) & 1, kx0 = (ox + 1) & 1;
    const int lyA = ((oy + 1 - ky0) >> 1) - y0;
    const int lxA = ((ox + 1 - kx0) >> 1) - x0;   // second position: +8

    u64 a[2][3];
#pragma unroll
    for (int q = 0; q < 2; q++)
#pragma unroll
        for (int k = 0; k < 3; k++) a[q][k] = 0ull;

#pragma unroll
    for (int ty = 0; ty < 2; ty++) {
        int ky = ky0 + 2 * ty, ly = lyA - ty;
#pragma unroll
        for (int tx = 0; tx < 2; tx++) {
            int kx = kx0 + 2 * tx;
            const ulonglong2* ip0 = (const ulonglong2*)&in_s[(ly * 18 + lxA - tx) * 132];
            const ulonglong2* ip1 = (const ulonglong2*)&in_s[(ly * 18 + lxA + 8 - tx) * 132];
            const ulonglong2* w0 = (const ulonglong2*)&w_s[((ky * 4 + kx) * 3 + 0) * 128];
            const ulonglong2* w1 = (const ulonglong2*)&w_s[((ky * 4 + kx) * 3 + 1) * 128];
            const ulonglong2* w2 = (const ulonglong2*)&w_s[((ky * 4 + kx) * 3 + 2) * 128];
#pragma unroll 8
            for (int c = 0; c < 32; c++) {
                ulonglong2 v0 = w0[c], v1 = w1[c], v2 = w2[c];
                ulonglong2 i0 = ip0[c], i1 = ip1[c];
                fma2(a[0][0], i0.x, v0.x); fma2(a[0][0], i0.y, v0.y);
                fma2(a[0][1], i0.x, v1.x); fma2(a[0][1], i0.y, v1.y);
                fma2(a[0][2], i0.x, v2.x); fma2(a[0][2], i0.y, v2.y);
                fma2(a[1][0], i1.x, v0.x); fma2(a[1][0], i1.y, v0.y);
                fma2(a[1][1], i1.x, v1.x); fma2(a[1][1], i1.y, v1.y);
                fma2(a[1][2], i1.x, v2.x); fma2(a[1][2], i1.y, v2.y);
            }
        }
    }
#pragma unroll
    for (int q = 0; q < 2; q++) {
        int oxq = ox + 16 * q;
        float2 r0 = unpack2(a[q][0]), r1 = unpack2(a[q][1]), r2 = unpack2(a[q][2]);
        out[(((size_t)n * 3 + 0) * 256 + oy) * 256 + oxq] = tanhf(r0.x + r0.y + b[0]);
        out[(((size_t)n * 3 + 1) * 256 + oy) * 256 + oxq] = tanhf(r1.x + r1.y + b[1]);
        out[(((size_t)n * 3 + 2) * 256 + oy) * 256 + oxq] = tanhf(r2.x + r2.y + b[2]);
    }
}

// deterministic loss finalize: vq_loss = 1.25 * sum / (131072*64)
__global__ void k_loss(float* __restrict__ out, int out_size) {
    __shared__ float red[256];
    int tid = threadIdx.x;
    red[tid] = g_part[tid] + g_part[tid + 256];
    __syncthreads();
    for (int st = 128; st > 0; st >>= 1) {
        if (tid < st) red[tid] += red[tid + st];
        __syncthreads();
    }
    if (tid == 0) out[out_size - 1] = 1.25f * red[0] / 8388608.0f;
}

extern "C" void kernel_launch(void* const* d_in, const int* in_sizes, int n_in,
                              void* d_out, int out_size) {
    const float* x   = (const float*)d_in[0];
    const float* ew1 = (const float*)d_in[1];
    const float* eb1 = (const float*)d_in[2];
    const float* ew2 = (const float*)d_in[3];
    const float* eb2 = (const float*)d_in[4];
    const float* cb  = (const float*)d_in[5];
    const float* dw1 = (const float*)d_in[6];
    const float* db1 = (const float*)d_in[7];
    const float* dw2 = (const float*)d_in[8];
    const float* db2 = (const float*)d_in[9];
    float* out = (float*)d_out;

    const int smem_conv2   = (9800 + 8192) * 4;
    const int smem_vq      = (32768 + 512 + 256) * 4;
    const int smem_deconv1 = (6800 + 16384) * 4;
    const int smem_deconv2 = (23760 + 6144) * 4;

    cudaFuncSetAttribute(k_conv2, cudaFuncAttributeMaxDynamicSharedMemorySize, smem_conv2);
    cudaFuncSetAttribute(k_vq, cudaFuncAttributeMaxDynamicSharedMemorySize, smem_vq);
    cudaFuncSetAttribute(k_deconv1, cudaFuncAttributeMaxDynamicSharedMemorySize, smem_deconv1);
    cudaFuncSetAttribute(k_deconv2, cudaFuncAttributeMaxDynamicSharedMemorySize, smem_deconv2);

    k_conv1<<<dim3(8, 8, 32), 512>>>(x, ew1, eb1);
    k_conv2<<<dim3(4, 4, 32), 256, smem_conv2>>>(ew2, eb2);
    k_vq<<<512, 256, smem_vq>>>(cb);
    k_deconv1<<<dim3(8, 8, 32), 512, smem_deconv1>>>(dw1, db1);
    k_deconv2<<<dim3(8, 16, 32), 256, smem_deconv2>>>(dw2, db2, out);
    k_loss<<<1, 256>>>(out, out_size);
}

// round 6
// speedup vs baseline: 1.5939x; 1.2748x over previous
#include <cuda_runtime.h>
#include <math.h>

// ---------------------------------------------------------------------------
// VQ-VAE forward, fp32 packed f32x2, conflict-free shared layouts, sm_103a
// ---------------------------------------------------------------------------

typedef unsigned long long u64;

__device__ __forceinline__ u64 bcast2(float v) {
    u64 r; asm("mov.b64 %0, {%1, %1};" : "=l"(r) : "f"(v)); return r;
}
__device__ __forceinline__ void fma2(u64& d, u64 a, u64 b) {
    asm("fma.rn.f32x2 %0, %1, %2, %0;" : "+l"(d) : "l"(a), "l"(b));
}
__device__ __forceinline__ float2 unpack2(u64 v) {
    float2 r; asm("mov.b64 {%0, %1}, %2;" : "=f"(r.x), "=f"(r.y) : "l"(v)); return r;
}

__device__ float g_big[67108864];            // 32*128*128*128
__device__ float g_z[8388608];               // 32*64*64*64 NHWC
__device__ float g_q[8388608];
__device__ float g_part[512];

// ===========================================================================
// conv1: x(32,3,256,256) * enc_w1(128,3,4,4) s2 p1 + b, ReLU -> z1 NCHW
// tile 32 cols x 8 rows, grid (4,16,32), block 512 = 8 ocg x 2 rw x 32 lanes
// input tile parity-split: in_s[(ic*19+row)*96 + (col&1)*48 + (col>>1)]
// ===========================================================================
__global__ void __launch_bounds__(512) k_conv1(const float* __restrict__ x,
                                               const float* __restrict__ w,
                                               const float* __restrict__ b) {
    __shared__ __align__(16) float w_s[16 * 3 * 128];        // [tap][ic][oc]
    __shared__ __align__(16) float in_s[3 * 19 * 96];        // 5472
    const int n = blockIdx.z;
    const int Tx = blockIdx.x * 32, Ty = blockIdx.y * 8;
    const int tid = threadIdx.x;
    const int lane = tid & 31, wid = tid >> 5;
    const int ocg = wid >> 1, rw = wid & 1;
    const int oc16 = ocg * 16;

    {
        const float4* w4 = (const float4*)w;
        for (int i = tid; i < 1536; i += 512) {
            int t4 = i & 3, rest = i >> 2;
            int ic = rest % 3, oc = rest / 3;
            float4 v = w4[(oc * 3 + ic) * 4 + t4];
            int base = ((t4 * 4) * 3 + ic) * 128 + oc;
            w_s[base + 0 * 3 * 128] = v.x;
            w_s[base + 1 * 3 * 128] = v.y;
            w_s[base + 2 * 3 * 128] = v.z;
            w_s[base + 3 * 3 * 128] = v.w;
        }
    }
    const int iy0 = 2 * Ty - 1, ix0 = 2 * Tx - 1;
    for (int i = tid; i < 3 * 19 * 67; i += 512) {
        int ic = i / (19 * 67), r = i % (19 * 67);
        int row = r / 67, col = r % 67;
        int gy = iy0 + row, gx = ix0 + col;
        float v = 0.f;
        if (gy >= 0 && gy < 256 && gx >= 0 && gx < 256)
            v = x[((n * 3 + ic) * 256 + gy) * 256 + gx];
        in_s[(ic * 19 + row) * 96 + (col & 1) * 48 + (col >> 1)] = v;
    }
    __syncthreads();

    u64 acc[4][8];
#pragma unroll
    for (int pp = 0; pp < 4; pp++)
#pragma unroll
        for (int k = 0; k < 8; k++) acc[pp][k] = 0ull;

    for (int ic = 0; ic < 3; ic++) {
#pragma unroll
        for (int ky = 0; ky < 4; ky++) {
#pragma unroll
            for (int kx = 0; kx < 4; kx++) {
                const ulonglong2* wp =
                    (const ulonglong2*)&w_s[((ky * 4 + kx) * 3 + ic) * 128 + oc16];
                ulonglong2 w0 = wp[0], w1 = wp[1], w2 = wp[2], w3 = wp[3];
                int coff = (kx & 1) * 48 + lane + (kx >> 1);
#pragma unroll
                for (int pp = 0; pp < 4; pp++) {
                    int tr = 2 * rw + 4 * pp + ky;   // tile row
                    u64 iv = bcast2(in_s[(ic * 19 + tr) * 96 + coff]);
                    fma2(acc[pp][0], iv, w0.x); fma2(acc[pp][1], iv, w0.y);
                    fma2(acc[pp][2], iv, w1.x); fma2(acc[pp][3], iv, w1.y);
                    fma2(acc[pp][4], iv, w2.x); fma2(acc[pp][5], iv, w2.y);
                    fma2(acc[pp][6], iv, w3.x); fma2(acc[pp][7], iv, w3.y);
                }
            }
        }
    }
    const int ox = Tx + lane;
#pragma unroll
    for (int pp = 0; pp < 4; pp++) {
        int oy = Ty + rw + 2 * pp;
#pragma unroll
        for (int k = 0; k < 8; k++) {
            float2 v = unpack2(acc[pp][k]);
            int oc = oc16 + 2 * k;
            g_big[((n * 128 + oc) * 128 + oy) * 128 + ox]     = fmaxf(v.x + b[oc], 0.f);
            g_big[((n * 128 + oc + 1) * 128 + oy) * 128 + ox] = fmaxf(v.y + b[oc + 1], 0.f);
        }
    }
}

// ===========================================================================
// conv2: z1 NCHW * enc_w2(64,128,4,4) s2 p1 + b -> g_z NHWC(32,64,64,64)
// tile 32 cols x 16 rows, grid (2,4,32), block 512 = 4 ocg x 4 rw x 32 lanes
// ic chunked by 4 over 32 chunks (128 ic total)
// ===========================================================================
__global__ void __launch_bounds__(512) k_conv2(const float* __restrict__ w,
                                               const float* __restrict__ b) {
    extern __shared__ float sm[];
    float* in_s = sm;            // 4*35*96 = 13440
    float* w_s = sm + 13440;     // 16*4*64 = 4096
    const int n = blockIdx.z;
    const int Tx = blockIdx.x * 32, Ty = blockIdx.y * 16;
    const int tid = threadIdx.x;
    const int lane = tid & 31, wid = tid >> 5;
    const int ocg = wid >> 2, rw = wid & 3;
    const int oc16 = ocg * 16;
    const int iy0 = 2 * Ty - 1, ix0 = 2 * Tx - 1;

    u64 acc[4][8];
#pragma unroll
    for (int pp = 0; pp < 4; pp++)
#pragma unroll
        for (int k = 0; k < 8; k++) acc[pp][k] = 0ull;

    const float4* w4 = (const float4*)w;
    for (int cc = 0; cc < 32; cc++) {           // 32 chunks x 4 ic = 128 ic
        __syncthreads();
        // w_s[(tap*4+ic4)*64+oc] = w[(oc*128 + cc*4+ic4)*16 + tap]
        for (int i = tid; i < 1024; i += 512) {
            int t4 = i & 3, ic4 = (i >> 2) & 3, oc = i >> 4;
            float4 v = w4[(oc * 128 + cc * 4 + ic4) * 4 + t4];
            int base = ((t4 * 4) * 4 + ic4) * 64 + oc;
            w_s[base + 0 * 4 * 64] = v.x;
            w_s[base + 1 * 4 * 64] = v.y;
            w_s[base + 2 * 4 * 64] = v.z;
            w_s[base + 3 * 4 * 64] = v.w;
        }
        for (int i = tid; i < 4 * 35 * 67; i += 512) {
            int ic4 = i / (35 * 67), r = i % (35 * 67);
            int row = r / 67, col = r % 67;
            int gy = iy0 + row, gx = ix0 + col;
            float v = 0.f;
            if (gy >= 0 && gy < 128 && gx >= 0 && gx < 128)
                v = g_big[((n * 128 + cc * 4 + ic4) * 128 + gy) * 128 + gx];
            in_s[(ic4 * 35 + row) * 96 + (col & 1) * 48 + (col >> 1)] = v;
        }
        __syncthreads();

        for (int ic4 = 0; ic4 < 4; ic4++) {
#pragma unroll
            for (int ky = 0; ky < 4; ky++) {
#pragma unroll
                for (int kx = 0; kx < 4; kx++) {
                    const ulonglong2* wp =
                        (const ulonglong2*)&w_s[((ky * 4 + kx) * 4 + ic4) * 64 + oc16];
                    ulonglong2 w0 = wp[0], w1 = wp[1], w2 = wp[2], w3 = wp[3];
                    int coff = (kx & 1) * 48 + lane + (kx >> 1);
#pragma unroll
                    for (int pp = 0; pp < 4; pp++) {
                        int tr = 2 * rw + 8 * pp + ky;
                        u64 iv = bcast2(in_s[(ic4 * 35 + tr) * 96 + coff]);
                        fma2(acc[pp][0], iv, w0.x); fma2(acc[pp][1], iv, w0.y);
                        fma2(acc[pp][2], iv, w1.x); fma2(acc[pp][3], iv, w1.y);
                        fma2(acc[pp][4], iv, w2.x); fma2(acc[pp][5], iv, w2.y);
                        fma2(acc[pp][6], iv, w3.x); fma2(acc[pp][7], iv, w3.y);
                    }
                }
            }
        }
    }
    const int ox = Tx + lane;
#pragma unroll
    for (int pp = 0; pp < 4; pp++) {
        int oy = Ty + rw + 4 * pp;
        float4* zp = (float4*)&g_z[((n * 64 + oy) * 64 + ox) * 64 + oc16];
#pragma unroll
        for (int k = 0; k < 4; k++) {
            float2 p0 = unpack2(acc[pp][2 * k]), p1 = unpack2(acc[pp][2 * k + 1]);
            float4 v;
            v.x = p0.x + b[oc16 + 4 * k + 0];
            v.y = p0.y + b[oc16 + 4 * k + 1];
            v.z = p1.x + b[oc16 + 4 * k + 2];
            v.w = p1.y + b[oc16 + 4 * k + 3];
            zp[k] = v;
        }
    }
}

// ===========================================================================
// VQ: argmin over 512 codes (D=64), gather, loss partial
// ===========================================================================
__global__ void __launch_bounds__(256) k_vq(const float* __restrict__ cb) {
    extern __shared__ float sm[];
    float* cb_s = sm;               // 512*64
    float* ccn = sm + 32768;        // 512
    float* red = ccn + 512;         // 256
    const int tid = threadIdx.x;

    for (int i = tid; i < 32768; i += 256) cb_s[i] = cb[i];
    __syncthreads();
    for (int j = tid; j < 512; j += 256) {
        float s = 0.f;
        const float* cp = &cb_s[j * 64];
        for (int d = 0; d < 64; d++) s = fmaf(cp[d], cp[d], s);
        ccn[j] = s;
    }
    __syncthreads();

    const int i = blockIdx.x * 256 + tid;
    u64 zr[32];
    {
        const ulonglong2* zp = (const ulonglong2*)&g_z[(size_t)i * 64];
#pragma unroll
        for (int d = 0; d < 16; d++) {
            ulonglong2 t = zp[d];
            zr[2 * d] = t.x; zr[2 * d + 1] = t.y;
        }
    }

    float best = 3.4e38f;
    int bi = 0;
    for (int j = 0; j < 512; j++) {
        const ulonglong2* cp = (const ulonglong2*)&cb_s[j * 64];
        u64 s2 = 0ull;
#pragma unroll
        for (int d = 0; d < 16; d++) {
            ulonglong2 c = cp[d];
            fma2(s2, zr[2 * d], c.x);
            fma2(s2, zr[2 * d + 1], c.y);
        }
        float2 ss = unpack2(s2);
        float score = ccn[j] - 2.f * (ss.x + ss.y);
        if (score < best) { best = score; bi = j; }
    }

    float4* qp = (float4*)&g_q[(size_t)i * 64];
    const float4* cp4 = (const float4*)&cb_s[bi * 64];
    const float4* zp4 = (const float4*)&g_z[(size_t)i * 64];
    float sq = 0.f;
#pragma unroll
    for (int d = 0; d < 16; d++) {
        float4 c = cp4[d], z = zp4[d];
        qp[d] = c;
        float dx = c.x - z.x, dy = c.y - z.y;
        float dz = c.z - z.z, dw = c.w - z.w;
        sq += dx * dx + dy * dy + dz * dz + dw * dw;
    }
    red[tid] = sq;
    __syncthreads();
    for (int st = 128; st > 0; st >>= 1) {
        if (tid < st) red[tid] += red[tid + st];
        __syncthreads();
    }
    if (tid == 0) g_part[blockIdx.x] = red[0];
}

// ===========================================================================
// deconv1: q NHWC ^T-conv dec_w1(64,128,4,4) s2 p1 + b, ReLU -> h NHWC
// tile 32 cols x 8 rows, grid (4,16,32), block 512 = 8 ocg x 2 rw x 32 lanes
// ic chunked by 8; in_s[(ic8*6+row)*18+col]; w_s[tap*1060 + ic8*132 + oc]
// ===========================================================================
__global__ void __launch_bounds__(512) k_deconv1(const float* __restrict__ w,
                                                 const float* __restrict__ b) {
    extern __shared__ float sm[];
    float* in_s = sm;            // 8*6*18 = 864
    float* w_s = sm + 864;       // 16*1060 = 16960
    const int n = blockIdx.z;
    const int Tx = blockIdx.x * 32, Ty = blockIdx.y * 8;
    const int tid = threadIdx.x;
    const int lane = tid & 31, wid = tid >> 5;
    const int ocg = wid >> 1, rw = wid & 1;
    const int oc16 = ocg * 16;

    const int ox = Tx + lane;
    const int ky0 = (Ty + rw + 1) & 1;            // oy parity uniform over pp
    const int kx0 = (ox + 1) & 1;
    const int y0 = (Ty >> 1) - 1, x0 = (Tx >> 1) - 1;
    const int lyA0 = ((Ty + rw + 1 - ky0) >> 1) - y0;     // + pp per step
    const int lxA = ((ox + 1 - kx0) >> 1) - x0;

    u64 acc[4][8];
#pragma unroll
    for (int pp = 0; pp < 4; pp++)
#pragma unroll
        for (int k = 0; k < 8; k++) acc[pp][k] = 0ull;

    const float4* w4 = (const float4*)w;
    for (int cc = 0; cc < 8; cc++) {
        __syncthreads();
        // weights: w_s[tap*1060 + ic8*132 + oc] = w[((cc*8+ic8)*128+oc)*16+tap]
        for (int i = tid; i < 4096; i += 512) {
            int t4 = i & 3, oc = (i >> 2) & 127, ic8 = i >> 9;
            float4 v = w4[((cc * 8 + ic8) * 128 + oc) * 4 + t4];
            int base = (t4 * 4) * 1060 + ic8 * 132 + oc;
            w_s[base + 0 * 1060] = v.x;
            w_s[base + 1 * 1060] = v.y;
            w_s[base + 2 * 1060] = v.z;
            w_s[base + 3 * 1060] = v.w;
        }
        // input 8 ic x 6 rows x 18 cols
        for (int i = tid; i < 864; i += 512) {
            int ic8 = i & 7, pos = i >> 3;
            int row = pos / 18, col = pos % 18;
            int gy = y0 + row, gx = x0 + col;
            float v = 0.f;
            if (gy >= 0 && gy < 64 && gx >= 0 && gx < 64)
                v = g_q[(((size_t)n * 64 + gy) * 64 + gx) * 64 + cc * 8 + ic8];
            in_s[(ic8 * 6 + row) * 18 + col] = v;
        }
        __syncthreads();

        for (int ic8 = 0; ic8 < 8; ic8++) {
#pragma unroll
            for (int ty = 0; ty < 2; ty++) {
                int ky = ky0 + 2 * ty;
#pragma unroll
                for (int tx = 0; tx < 2; tx++) {
                    int kx = kx0 + 2 * tx;
                    const ulonglong2* wp =
                        (const ulonglong2*)&w_s[(ky * 4 + kx) * 1060 + ic8 * 132 + oc16];
                    ulonglong2 w0 = wp[0], w1 = wp[1], w2 = wp[2], w3 = wp[3];
                    int lx = lxA - tx;
#pragma unroll
                    for (int pp = 0; pp < 4; pp++) {
                        int ly = lyA0 + pp - ty;
                        u64 iv = bcast2(in_s[(ic8 * 6 + ly) * 18 + lx]);
                        fma2(acc[pp][0], iv, w0.x); fma2(acc[pp][1], iv, w0.y);
                        fma2(acc[pp][2], iv, w1.x); fma2(acc[pp][3], iv, w1.y);
                        fma2(acc[pp][4], iv, w2.x); fma2(acc[pp][5], iv, w2.y);
                        fma2(acc[pp][6], iv, w3.x); fma2(acc[pp][7], iv, w3.y);
                    }
                }
            }
        }
    }
#pragma unroll
    for (int pp = 0; pp < 4; pp++) {
        int oy = Ty + rw + 2 * pp;
        float4* hp = (float4*)&g_big[(((size_t)n * 128 + oy) * 128 + ox) * 128 + oc16];
#pragma unroll
        for (int k = 0; k < 4; k++) {
            float2 p0 = unpack2(acc[pp][2 * k]), p1 = unpack2(acc[pp][2 * k + 1]);
            float4 v;
            v.x = fmaxf(p0.x + b[oc16 + 4 * k + 0], 0.f);
            v.y = fmaxf(p0.y + b[oc16 + 4 * k + 1], 0.f);
            v.z = fmaxf(p1.x + b[oc16 + 4 * k + 2], 0.f);
            v.w = fmaxf(p1.y + b[oc16 + 4 * k + 3], 0.f);
            hp[k] = v;
        }
    }
}

// ===========================================================================
// deconv2: h NHWC ^T-conv dec_w2(128,3,4,4) s2 p1 + b, tanh -> out NCHW
// grid (8,16,32), tile 16 rows x 32 cols, block 256: 2 positions/thread
// ===========================================================================
__global__ void __launch_bounds__(256) k_deconv2(const float* __restrict__ w,
                                                 const float* __restrict__ b,
                                                 float* __restrict__ out) {
    extern __shared__ float sm[];
    float* in_s = sm;             // 180*132 = 23760
    float* w_s = sm + 23760;      // 6144
    const int n = blockIdx.z;
    const int Tx = blockIdx.x * 32, Ty = blockIdx.y * 16;
    const int tid = threadIdx.x;
    const int py = tid >> 4, px = tid & 15;
    const int oy = Ty + py, ox = Tx + px;
    const int y0 = (Ty >> 1) - 1, x0 = (Tx >> 1) - 1;

    {
        const float4* w4 = (const float4*)w;
        for (int i = tid; i < 1536; i += 256) {
            int t4 = i & 3, rest = i >> 2;
            int oc = rest % 3, ic = rest / 3;
            float4 v = w4[(ic * 3 + oc) * 4 + t4];
            int base = ((t4 * 4) * 3 + oc) * 128 + ic;
            w_s[base + 0 * 3 * 128] = v.x;
            w_s[base + 1 * 3 * 128] = v.y;
            w_s[base + 2 * 3 * 128] = v.z;
            w_s[base + 3 * 3 * 128] = v.w;
        }
    }
    for (int i = tid; i < 23040; i += 256) {
        int ic = i & 127, pos = i >> 7;
        int ly = pos / 18, lx = pos % 18;
        int gy = y0 + ly, gx = x0 + lx;
        float v = 0.f;
        if (gy >= 0 && gy < 128 && gx >= 0 && gx < 128)
            v = g_big[(((size_t)n * 128 + gy) * 128 + gx) * 128 + ic];
        in_s[pos * 132 + ic] = v;
    }
    __syncthreads();

    const int ky0 = (oy + 1) & 1, kx0 = (ox + 1) & 1;
    const int lyA = ((oy + 1 - ky0) >> 1) - y0;
    const int lxA = ((ox + 1 - kx0) >> 1) - x0;

    u64 a[2][3];
#pragma unroll
    for (int q = 0; q < 2; q++)
#pragma unroll
        for (int k = 0; k < 3; k++) a[q][k] = 0ull;

#pragma unroll
    for (int ty = 0; ty < 2; ty++) {
        int ky = ky0 + 2 * ty, ly = lyA - ty;
#pragma unroll
        for (int tx = 0; tx < 2; tx++) {
            int kx = kx0 + 2 * tx;
            const ulonglong2* ip0 = (const ulonglong2*)&in_s[(ly * 18 + lxA - tx) * 132];
            const ulonglong2* ip1 = (const ulonglong2*)&in_s[(ly * 18 + lxA + 8 - tx) * 132];
            const ulonglong2* w0 = (const ulonglong2*)&w_s[((ky * 4 + kx) * 3 + 0) * 128];
            const ulonglong2* w1 = (const ulonglong2*)&w_s[((ky * 4 + kx) * 3 + 1) * 128];
            const ulonglong2* w2 = (const ulonglong2*)&w_s[((ky * 4 + kx) * 3 + 2) * 128];
#pragma unroll 8
            for (int c = 0; c < 32; c++) {
                ulonglong2 v0 = w0[c], v1 = w1[c], v2 = w2[c];
                ulonglong2 i0 = ip0[c], i1 = ip1[c];
                fma2(a[0][0], i0.x, v0.x); fma2(a[0][0], i0.y, v0.y);
                fma2(a[0][1], i0.x, v1.x); fma2(a[0][1], i0.y, v1.y);
                fma2(a[0][2], i0.x, v2.x); fma2(a[0][2], i0.y, v2.y);
                fma2(a[1][0], i1.x, v0.x); fma2(a[1][0], i1.y, v0.y);
                fma2(a[1][1], i1.x, v1.x); fma2(a[1][1], i1.y, v1.y);
                fma2(a[1][2], i1.x, v2.x); fma2(a[1][2], i1.y, v2.y);
            }
        }
    }
#pragma unroll
    for (int q = 0; q < 2; q++) {
        int oxq = ox + 16 * q;
        float2 r0 = unpack2(a[q][0]), r1 = unpack2(a[q][1]), r2 = unpack2(a[q][2]);
        out[(((size_t)n * 3 + 0) * 256 + oy) * 256 + oxq] = tanhf(r0.x + r0.y + b[0]);
        out[(((size_t)n * 3 + 1) * 256 + oy) * 256 + oxq] = tanhf(r1.x + r1.y + b[1]);
        out[(((size_t)n * 3 + 2) * 256 + oy) * 256 + oxq] = tanhf(r2.x + r2.y + b[2]);
    }
}

// deterministic loss finalize: vq_loss = 1.25 * sum / (131072*64)
__global__ void k_loss(float* __restrict__ out, int out_size) {
    __shared__ float red[256];
    int tid = threadIdx.x;
    red[tid] = g_part[tid] + g_part[tid + 256];
    __syncthreads();
    for (int st = 128; st > 0; st >>= 1) {
        if (tid < st) red[tid] += red[tid + st];
        __syncthreads();
    }
    if (tid == 0) out[out_size - 1] = 1.25f * red[0] / 8388608.0f;
}

extern "C" void kernel_launch(void* const* d_in, const int* in_sizes, int n_in,
                              void* d_out, int out_size) {
    const float* x   = (const float*)d_in[0];
    const float* ew1 = (const float*)d_in[1];
    const float* eb1 = (const float*)d_in[2];
    const float* ew2 = (const float*)d_in[3];
    const float* eb2 = (const float*)d_in[4];
    const float* cb  = (const float*)d_in[5];
    const float* dw1 = (const float*)d_in[6];
    const float* db1 = (const float*)d_in[7];
    const float* dw2 = (const float*)d_in[8];
    const float* db2 = (const float*)d_in[9];
    float* out = (float*)d_out;

    const int smem_conv2   = (13440 + 4096) * 4;   // 70144
    const int smem_vq      = (32768 + 512 + 256) * 4;
    const int smem_deconv1 = (864 + 16960) * 4;    // 71296
    const int smem_deconv2 = (23760 + 6144) * 4;

    cudaFuncSetAttribute(k_conv2, cudaFuncAttributeMaxDynamicSharedMemorySize, smem_conv2);
    cudaFuncSetAttribute(k_vq, cudaFuncAttributeMaxDynamicSharedMemorySize, smem_vq);
    cudaFuncSetAttribute(k_deconv1, cudaFuncAttributeMaxDynamicSharedMemorySize, smem_deconv1);
    cudaFuncSetAttribute(k_deconv2, cudaFuncAttributeMaxDynamicSharedMemorySize, smem_deconv2);

    k_conv1<<<dim3(4, 16, 32), 512>>>(x, ew1, eb1);
    k_conv2<<<dim3(2, 4, 32), 512, smem_conv2>>>(ew2, eb2);
    k_vq<<<512, 256, smem_vq>>>(cb);
    k_deconv1<<<dim3(4, 16, 32), 512, smem_deconv1>>>(dw1, db1);
    k_deconv2<<<dim3(8, 16, 32), 256, smem_deconv2>>>(dw2, db2, out);
    k_loss<<<1, 256>>>(out, out_size);
}